// round 10
// baseline (speedup 1.0000x reference)
#include <cuda_runtime.h>

#define NJ 24
#define BB 32                 // bodies per block
#define T  96                 // 3 warps: warp r owns row r of each body
#define PSTR 19               // pos stride per body in float4 (76 words: conflict-free)

#define CP_ASYNC16(dst, src) \
    asm volatile("cp.async.cg.shared.global [%0], [%1], 16;" :: "r"(dst), "l"(src) : "memory")
#define CP_COMMIT()  asm volatile("cp.async.commit_group;" ::: "memory")
#define CP_WAIT0()   asm volatile("cp.async.wait_group 0;" ::: "memory")

__device__ __forceinline__ unsigned s2u(const void* p) {
    return (unsigned)__cvta_generic_to_shared(p);
}

__global__ __launch_bounds__(T, 10)
void fk_kernel(const float4* __restrict__ rot4,   // [nB*24] quats
               const float4* __restrict__ pos4,   // [nB*18] packed positions
               float4*       __restrict__ out4,   // [nB*18] packed output
               int numTiles, int nB)
{
    __shared__ float4 qs[NJ * BB];      // 12288 B: quats in, globals out (reused)
    __shared__ float4 pd[BB * PSTR];    //  9728 B: positions, padded stride

    const int t = threadIdx.x;
    constexpr int PAR[NJ] = {-1,0,0,0,1,2,3,4,5,6,7,8,9,9,9,12,13,14,16,17,18,19,20,21};

    if (blockIdx.x < (unsigned)numTiles) {
        const int tile = blockIdx.x;
        const float4* qsrc = rot4 + (size_t)tile * (BB * NJ);
        const float4* psrc = pos4 + (size_t)tile * (BB * 18);

        // ---- stage: coalesced cp.async (768 quat f4 + 576 pos f4 over 96 thr) ----
#pragma unroll
        for (int k = 0; k < 8; ++k) {
            int idx  = k * T + t;
            int body = idx / NJ;
            int j    = idx - body * NJ;
            CP_ASYNC16(s2u(qs + (j * BB + (body ^ j))), qsrc + idx);
        }
#pragma unroll
        for (int k = 0; k < 6; ++k) {
            int idx  = k * T + t;
            int body = idx / 18;
            int kk   = idx - body * 18;
            CP_ASYNC16(s2u(pd + (body * PSTR + kk)), psrc + idx);
        }
        CP_COMMIT();
        CP_WAIT0();
        __syncthreads();

        // ---- compute: warp r owns row r of body (lane) ----
        const int b = t & 31;            // body  = lane
        const int r = t >> 5;            // row   = warp id (uniform per warp)

        float Rr[NJ][3];                 // row r of global rotation per joint
        float Gr[NJ];                    // component r of global translation
        float pl[12];                    // 4 joints' local positions

#pragma unroll
        for (int j = 0; j < NJ; ++j) {
            if ((j & 3) == 0) {          // 3x LDS.128 -> next 4 joints' positions
                const int g = j >> 2;
#pragma unroll
                for (int m = 0; m < 3; ++m) {
                    float4 v = pd[b * PSTR + 3 * g + m];
                    pl[4*m+0] = v.x; pl[4*m+1] = v.y; pl[4*m+2] = v.z; pl[4*m+3] = v.w;
                }
            }
            float4 q = qs[j * BB + (b ^ j)];
            float w = q.x, x = q.y, y = q.z, z = q.w;
            float sc = 2.0f / (w*w + x*x + y*y + z*z);   // == normalize-then-rotmat
            float xs = x*sc, ys = y*sc, zs = z*sc;
            float wx = w*xs, wy = w*ys, wz = w*zs;
            float xx = x*xs, xy = x*ys, xz = x*zs;
            float yy = y*ys, yz = y*zs, zz = z*zs;

            float Rl[9] = {1.0f-(yy+zz), xy-wz,        xz+wy,
                           xy+wz,        1.0f-(xx+zz), yz-wx,
                           xz-wy,        yz+wx,        1.0f-(xx+yy)};

            const int d3 = 3 * (j & 3);
            float t0 = pl[d3+0], t1 = pl[d3+1], t2 = pl[d3+2];

            const int pa = PAR[j];
            if (pa < 0) {
                // row r of Rl (r warp-uniform -> cheap selects)
                Rr[j][0] = (r == 0) ? Rl[0] : (r == 1) ? Rl[3] : Rl[6];
                Rr[j][1] = (r == 0) ? Rl[1] : (r == 1) ? Rl[4] : Rl[7];
                Rr[j][2] = (r == 0) ? Rl[2] : (r == 1) ? Rl[5] : Rl[8];
                Gr[j]    = (r == 0) ? t0    : (r == 1) ? t1    : t2;
            } else {
#pragma unroll
                for (int c = 0; c < 3; ++c)
                    Rr[j][c] = Rr[pa][0]*Rl[0*3+c]
                             + Rr[pa][1]*Rl[1*3+c]
                             + Rr[pa][2]*Rl[2*3+c];
                Gr[j] = Rr[pa][0]*t0 + Rr[pa][1]*t1 + Rr[pa][2]*t2 + Gr[pa];
            }
        }
        __syncthreads();                 // all quat/pos reads complete

        // ---- scatter globals into qs region (word b*76 + 3j + r) ----
        {
            float* qf = reinterpret_cast<float*>(qs);
#pragma unroll
            for (int j = 0; j < NJ; ++j)
                qf[b * 76 + 3 * j + r] = Gr[j];
        }
        __syncthreads();

        // ---- writeout: LDS.128 -> coalesced STG.128 ----
        float4* dst = out4 + (size_t)tile * (BB * 18);
#pragma unroll
        for (int k = 0; k < 6; ++k) {
            int idx  = k * T + t;
            int body = idx / 18;
            int kk   = idx - body * 18;
            dst[idx] = qs[body * PSTR + kk];
        }
    }

    // ---- remainder bodies (nB % 32 != 0; never taken for B=131072) ----
    const int rem = nB - numTiles * BB;
    if (rem > 0 && blockIdx.x == 0 && t < BB) {
        long long bb = (long long)numTiles * BB + t;
        if (bb < nB) {
            const float4* q4 = rot4 + bb * NJ;
            const float*  p  = (const float*)(pos4) + bb * 72;
            float*        o  = (float*)(out4) + bb * 72;
            float R[NJ][9], G[NJ][3];
#pragma unroll
            for (int j = 0; j < NJ; ++j) {
                float4 q = q4[j];
                float w = q.x, x = q.y, y = q.z, z = q.w;
                float sc = 2.0f / (w*w + x*x + y*y + z*z);
                float xs = x*sc, ys = y*sc, zs = z*sc;
                float wx = w*xs, wy = w*ys, wz = w*zs;
                float xx = x*xs, xy = x*ys, xz = x*zs;
                float yy = y*ys, yz = y*zs, zz = z*zs;
                float Rl[9] = {1.0f-(yy+zz), xy-wz, xz+wy,
                               xy+wz, 1.0f-(xx+zz), yz-wx,
                               xz-wy, yz+wx, 1.0f-(xx+yy)};
                float t0 = p[3*j+0], t1 = p[3*j+1], t2 = p[3*j+2];
                const int pa = PAR[j];
                if (pa < 0) {
#pragma unroll
                    for (int k = 0; k < 9; ++k) R[j][k] = Rl[k];
                    G[j][0] = t0; G[j][1] = t1; G[j][2] = t2;
                } else {
#pragma unroll
                    for (int rr = 0; rr < 3; ++rr)
#pragma unroll
                        for (int c = 0; c < 3; ++c)
                            R[j][rr*3+c] = R[pa][rr*3+0]*Rl[0*3+c]
                                         + R[pa][rr*3+1]*Rl[1*3+c]
                                         + R[pa][rr*3+2]*Rl[2*3+c];
                    G[j][0] = R[pa][0]*t0 + R[pa][1]*t1 + R[pa][2]*t2 + G[pa][0];
                    G[j][1] = R[pa][3]*t0 + R[pa][4]*t1 + R[pa][5]*t2 + G[pa][1];
                    G[j][2] = R[pa][6]*t0 + R[pa][7]*t1 + R[pa][8]*t2 + G[pa][2];
                }
                o[3*j+0] = G[j][0]; o[3*j+1] = G[j][1]; o[3*j+2] = G[j][2];
            }
        }
    }
}

extern "C" void kernel_launch(void* const* d_in, const int* in_sizes, int n_in,
                              void* d_out, int out_size)
{
    const float4* pos = (const float4*)d_in[1];
    const float4* rot = (const float4*)d_in[2];
    float4* out = (float4*)d_out;

    static bool init = false;
    if (!init) {
        cudaFuncSetAttribute(fk_kernel, cudaFuncAttributePreferredSharedMemoryCarveout, 100);
        init = true;
    }

    int nB = in_sizes[1] / (NJ * 3);     // 131072
    int numTiles = nB / BB;              // 4096
    int grid = numTiles + (nB % BB ? 1 : 0);
    fk_kernel<<<grid, T>>>(rot, pos, out, numTiles, nB);
}

// round 12
// speedup vs baseline: 1.0656x; 1.0656x over previous
#include <cuda_runtime.h>

#define NJ 24
#define BB 32                 // bodies per block (= threads per block)
#define T  32
#define PSTR 19               // pos stride per body in float4 (76 words: conflict-free)

#define CP_ASYNC16(dst, src) \
    asm volatile("cp.async.cg.shared.global [%0], [%1], 16;" :: "r"(dst), "l"(src) : "memory")
#define CP_COMMIT()  asm volatile("cp.async.commit_group;" ::: "memory")
#define CP_WAIT0()   asm volatile("cp.async.wait_group 0;" ::: "memory")

__device__ __forceinline__ unsigned s2u(const void* p) {
    return (unsigned)__cvta_generic_to_shared(p);
}

__global__ __launch_bounds__(T, 10)
void fk_kernel(const float4* __restrict__ rot4,   // [nB*24] quats (w,x,y,z)
               const float4* __restrict__ pos4,   // [nB*18] packed positions
               float4*       __restrict__ out4,   // [nB*18] packed output
               int numTiles, int nB)
{
    __shared__ float4 qs[NJ * BB];      // 12288 B, transposed + xor-swizzled
    __shared__ float4 pd[BB * PSTR];    //  9728 B, raw per-body, padded stride

    const int t = threadIdx.x;
    constexpr int PAR[NJ] = {-1,0,0,0,1,2,3,4,5,6,7,8,9,9,9,12,13,14,16,17,18,19,20,21};

    if (blockIdx.x < (unsigned)numTiles) {
        const int tile = blockIdx.x;
        const float4* qsrc = rot4 + (size_t)tile * (BB * NJ);
        const float4* psrc = pos4 + (size_t)tile * (BB * 18);

        // ---- stage: coalesced cp.async ----
#pragma unroll
        for (int k = 0; k < NJ; ++k) {             // 768 quat float4 / 32 thr
            const int base = k * T;                // compile-time
            int u = (base % NJ) + t;               // < 56
            int a = (u >= NJ) + (u >= 2 * NJ);
            int j    = u - a * NJ;                 // base+t == body*24 + j
            int body = base / NJ + a;
            CP_ASYNC16(s2u(qs + (j * BB + (body ^ j))), qsrc + (base + t));
        }
#pragma unroll
        for (int k = 0; k < 18; ++k) {             // 576 pos float4 / 32 thr
            const int base = k * T;
            int u = (base % 18) + t;               // < 50
            int a = (u >= 18) + (u >= 36);
            int kk   = u - a * 18;                 // base+t == body*18 + kk
            int body = base / 18 + a;
            CP_ASYNC16(s2u(pd + (body * PSTR + kk)), psrc + (base + t));
        }
        CP_COMMIT();
        CP_WAIT0();
        __syncwarp();

        // ---- compute: thread t owns body t; chain QUATERNIONS, not matrices ----
        float Qw[NJ], Qx[NJ], Qy[NJ], Qz[NJ];     // global orientation (unit quat)
        float Gx[NJ], Gy[NJ], Gz[NJ];             // global translation
        float pl[12];                              // 4 joints' local positions
        float gl[12];                              // 4 joints' global positions

#pragma unroll
        for (int j = 0; j < NJ; ++j) {
            if ((j & 3) == 0) {                    // 3x LDS.128 -> 4 joints' positions
                const int g = j >> 2;
#pragma unroll
                for (int m = 0; m < 3; ++m) {
                    float4 v = pd[t * PSTR + 3 * g + m];
                    pl[4*m+0] = v.x; pl[4*m+1] = v.y; pl[4*m+2] = v.z; pl[4*m+3] = v.w;
                }
            }
            float4 q = qs[j * BB + (t ^ j)];
            float w = q.x, x = q.y, y = q.z, z = q.w;
            float inv = rsqrtf(w*w + x*x + y*y + z*z);
            w *= inv; x *= inv; y *= inv; z *= inv;

            const int d3 = 3 * (j & 3);            // slot within pl/gl (0,3,6,9)
            float t0 = pl[d3+0], t1 = pl[d3+1], t2 = pl[d3+2];

            const int pa = PAR[j];
            if (pa < 0) {
                Qw[j] = w; Qx[j] = x; Qy[j] = y; Qz[j] = z;
                Gx[j] = t0; Gy[j] = t1; Gz[j] = t2;
            } else {
                float pw = Qw[pa], px = Qx[pa], py = Qy[pa], pz = Qz[pa];
                // global quat = parent ⊗ local  (Hamilton product)
                Qw[j] = pw*w - px*x - py*y - pz*z;
                Qx[j] = pw*x + px*w + py*z - pz*y;
                Qy[j] = pw*y - px*z + py*w + pz*x;
                Qz[j] = pw*z + px*y - py*x + pz*w;
                // rotate t by parent quat: v' = v + 2*pv×(pv×v + pw*v)
                float ux = py*t2 - pz*t1 + pw*t0;
                float uy = pz*t0 - px*t2 + pw*t1;
                float uz = px*t1 - py*t0 + pw*t2;
                float cx = py*uz - pz*uy;
                float cy = pz*ux - px*uz;
                float cz = px*uy - py*ux;
                Gx[j] = Gx[pa] + t0 + 2.0f*cx;
                Gy[j] = Gy[pa] + t1 + 2.0f*cy;
                Gz[j] = Gz[pa] + t2 + 2.0f*cz;
            }
            gl[d3+0] = Gx[j];
            gl[d3+1] = Gy[j];
            gl[d3+2] = Gz[j];
            if ((j & 3) == 3) {                    // overwrite consumed pos slots
                const int g = j >> 2;
#pragma unroll
                for (int m = 0; m < 3; ++m)
                    pd[t * PSTR + 3 * g + m] =
                        make_float4(gl[4*m+0], gl[4*m+1], gl[4*m+2], gl[4*m+3]);
            }
        }
        __syncwarp();

        // ---- writeout: LDS.128 -> coalesced STG.128 ----
        float4* dst = out4 + (size_t)tile * (BB * 18);
#pragma unroll
        for (int k = 0; k < 18; ++k) {
            const int base = k * T;
            int u = (base % 18) + t;
            int a = (u >= 18) + (u >= 36);
            int kk   = u - a * 18;
            int body = base / 18 + a;
            dst[base + t] = pd[body * PSTR + kk];
        }
    }

    // ---- remainder bodies (nB % 32 != 0; never taken for B=131072) ----
    const int rem = nB - numTiles * BB;
    if (rem > 0 && blockIdx.x == 0) {
        long long b = (long long)numTiles * BB + t;
        if (b < nB) {
            const float4* q4 = rot4 + b * NJ;
            const float*  p  = (const float*)(pos4) + b * 72;
            float*        o  = (float*)(out4) + b * 72;
            float Qw[NJ], Qx[NJ], Qy[NJ], Qz[NJ], Gx[NJ], Gy[NJ], Gz[NJ];
#pragma unroll
            for (int j = 0; j < NJ; ++j) {
                float4 q = q4[j];
                float w = q.x, x = q.y, y = q.z, z = q.w;
                float inv = rsqrtf(w*w + x*x + y*y + z*z);
                w *= inv; x *= inv; y *= inv; z *= inv;
                float t0 = p[3*j+0], t1 = p[3*j+1], t2 = p[3*j+2];
                const int pa = PAR[j];
                if (pa < 0) {
                    Qw[j] = w; Qx[j] = x; Qy[j] = y; Qz[j] = z;
                    Gx[j] = t0; Gy[j] = t1; Gz[j] = t2;
                } else {
                    float pw = Qw[pa], px = Qx[pa], py = Qy[pa], pz = Qz[pa];
                    Qw[j] = pw*w - px*x - py*y - pz*z;
                    Qx[j] = pw*x + px*w + py*z - pz*y;
                    Qy[j] = pw*y - px*z + py*w + pz*x;
                    Qz[j] = pw*z + px*y - py*x + pz*w;
                    float ux = py*t2 - pz*t1 + pw*t0;
                    float uy = pz*t0 - px*t2 + pw*t1;
                    float uz = px*t1 - py*t0 + pw*t2;
                    float cx = py*uz - pz*uy;
                    float cy = pz*ux - px*uz;
                    float cz = px*uy - py*ux;
                    Gx[j] = Gx[pa] + t0 + 2.0f*cx;
                    Gy[j] = Gy[pa] + t1 + 2.0f*cy;
                    Gz[j] = Gz[pa] + t2 + 2.0f*cz;
                }
                o[3*j+0] = Gx[j]; o[3*j+1] = Gy[j]; o[3*j+2] = Gz[j];
            }
        }
    }
}

extern "C" void kernel_launch(void* const* d_in, const int* in_sizes, int n_in,
                              void* d_out, int out_size)
{
    const float4* pos = (const float4*)d_in[1];
    const float4* rot = (const float4*)d_in[2];
    float4* out = (float4*)d_out;

    static bool init = false;
    if (!init) {
        cudaFuncSetAttribute(fk_kernel, cudaFuncAttributePreferredSharedMemoryCarveout, 100);
        init = true;
    }

    int nB = in_sizes[1] / (NJ * 3);     // 131072
    int numTiles = nB / BB;              // 4096
    int grid = numTiles + (nB % BB ? 1 : 0);
    fk_kernel<<<grid, T>>>(rot, pos, out, numTiles, nB);
}